// round 1
// baseline (speedup 1.0000x reference)
#include <cuda_runtime.h>
#include <math.h>

// Problem constants
#define Hn    81
#define G3    243          // 3*H
#define RPAD  244          // rows padded to even (122 pairs)
#define NPAIR 122
#define Fn    128
#define Tn    1024
#define Bn    512
#define BPC   4            // batches per CTA
#define NCTA  128          // 512 / 4
#define NTHR  128

// --- shared memory layout (bytes, all 16B aligned) ---
#define OFF_WIH 0
#define SZ_WIH  (Fn*NPAIR*8)           // 124928: W_ih^T row-paired  [k][pair] float2
#define OFF_WHH (OFF_WIH + SZ_WIH)     // 124928
#define SZ_WHH  (Hn*NPAIR*8)           // 79056:  W_hh^T row-paired
#define OFF_XS  (OFF_WHH + SZ_WHH)     // 203984
#define SZ_XS   (2*Fn*16)              // 4096: double-buffered x tile [buf][k] float4(4 batches)
#define OFF_HS  (OFF_XS + SZ_XS)       // 208080
#define SZ_HS   (84*16)                // 1344: h state [j] float4(4 batches), padded
#define OFF_XG  (OFF_HS + SZ_HS)       // 209424
#define SZ_XG   (RPAD*16)              // 3904
#define OFF_HG  (OFF_XG + SZ_XG)       // 213328
#define SZ_HG   (RPAD*16)              // 3904
#define OFF_BIH (OFF_HG + SZ_HG)       // 217232
#define SZ_BIH  (RPAD*4)               // 976
#define OFF_BHH (OFF_BIH + SZ_BIH)     // 218208
#define SZ_BHH  (RPAD*4)               // 976
#define SMEM_BYTES (OFF_BHH + SZ_BHH)  // 219184 < 227KB opt-in limit

// scratch: per-batch post-GRU fc output (silu(h @ fc_w^T + fc_b)) [512][8]
__device__ float g_h8[Bn * 8];

// ---------- packed f32x2 helpers (Blackwell FFMA2 path) ----------
static __device__ __forceinline__ unsigned long long dup2(float x) {
    unsigned long long r;
    asm("mov.b64 %0, {%1, %1};" : "=l"(r) : "f"(x));
    return r;
}
static __device__ __forceinline__ void ffma2(unsigned long long &d,
                                             unsigned long long a,
                                             unsigned long long b) {
    asm("fma.rn.f32x2 %0, %1, %2, %0;" : "+l"(d) : "l"(a), "l"(b));
}
static __device__ __forceinline__ float2 unpk(unsigned long long v) {
    float lo, hi;
    asm("mov.b64 {%0, %1}, %2;" : "=f"(lo), "=f"(hi) : "l"(v));
    return make_float2(lo, hi);
}

// ---------- accurate-enough fast activations ----------
static __device__ __forceinline__ float sigm(float x) {
    x = fminf(fmaxf(x, -30.f), 30.f);
    return __fdividef(1.f, 1.f + __expf(-x));
}
static __device__ __forceinline__ float tanh_f(float x) {
    x = fminf(fmaxf(x, -20.f), 20.f);
    float e = __expf(-2.f * x);
    return __fdividef(1.f - e, 1.f + e);
}

// =====================================================================
// Kernel 1: fused GRU over T=1024 steps. 128 CTAs x 4 batches.
// =====================================================================
__global__ void __launch_bounds__(NTHR, 1) gru_kernel(
    const float* __restrict__ x,     // [B,1,T,F]
    const float* __restrict__ W_ih,  // [3H,F]
    const float* __restrict__ W_hh,  // [3H,H]
    const float* __restrict__ b_ih,  // [3H]
    const float* __restrict__ b_hh,  // [3H]
    const float* __restrict__ fc_w,  // [8,H]
    const float* __restrict__ fc_b)  // [8]
{
    extern __shared__ char sm[];
    float2* wih2 = (float2*)(sm + OFF_WIH);
    float2* whh2 = (float2*)(sm + OFF_WHH);
    float*  xs_f = (float*)(sm + OFF_XS);
    float4* xs4  = (float4*)(sm + OFF_XS);
    float*  hs_f = (float*)(sm + OFF_HS);
    float*  xg_f = (float*)(sm + OFF_XG);
    float4* xg4  = (float4*)(sm + OFF_XG);
    float*  hg_f = (float*)(sm + OFF_HG);
    float4* hg4  = (float4*)(sm + OFF_HG);
    float*  bih  = (float*)(sm + OFF_BIH);
    float*  bhh  = (float*)(sm + OFF_BHH);

    const int tid = threadIdx.x;
    const int b0  = blockIdx.x * BPC;

    // ---- one-time init: transpose + row-pair weights into SMEM ----
    for (int idx = tid; idx < RPAD * Fn; idx += NTHR) {
        int k = idx & (Fn - 1);
        int r = idx >> 7;
        float v = (r < G3) ? W_ih[r * Fn + k] : 0.f;
        ((float*)wih2)[(k * NPAIR + (r >> 1)) * 2 + (r & 1)] = v;
    }
    for (int idx = tid; idx < RPAD * Hn; idx += NTHR) {
        int k = idx % Hn;
        int r = idx / Hn;
        float v = (r < G3) ? W_hh[r * Hn + k] : 0.f;
        ((float*)whh2)[(k * NPAIR + (r >> 1)) * 2 + (r & 1)] = v;
    }
    for (int idx = tid; idx < RPAD; idx += NTHR) {
        bih[idx] = (idx < G3) ? b_ih[idx] : 0.f;
        bhh[idx] = (idx < G3) ? b_hh[idx] : 0.f;
    }
    for (int idx = tid; idx < 84 * 4; idx += NTHR) hs_f[idx] = 0.f;

    // stage x(t=0): thread tid loads feature k=tid for all 4 batches
    {
        float p0 = x[(b0 + 0) * Tn * Fn + tid];
        float p1 = x[(b0 + 1) * Tn * Fn + tid];
        float p2 = x[(b0 + 2) * Tn * Fn + tid];
        float p3 = x[(b0 + 3) * Tn * Fn + tid];
        xs4[tid] = make_float4(p0, p1, p2, p3);
    }
    __syncthreads();

    const int g = tid;  // row-pair index (rows 2g, 2g+1), active for g < 122

    for (int t = 0; t < Tn; t++) {
        const int cur = t & 1, nxt = cur ^ 1;

        // prefetch x(t+1) into registers (hide DRAM latency behind compute)
        float p0 = 0.f, p1 = 0.f, p2 = 0.f, p3 = 0.f;
        const bool pf = (t + 1 < Tn);
        if (pf) {
            const float* xb = x + (t + 1) * Fn + tid;
            p0 = xb[(b0 + 0) * Tn * Fn];
            p1 = xb[(b0 + 1) * Tn * Fn];
            p2 = xb[(b0 + 2) * Tn * Fn];
            p3 = xb[(b0 + 3) * Tn * Fn];
        }

        if (g < NPAIR) {
            // ---- xg = x_t @ W_ih^T  (2 rows x 4 batches per thread, f32x2) ----
            unsigned long long a00 = 0, a01 = 0, a10 = 0, a11 = 0;
            const float2* wp = wih2 + g;
            const ulonglong2* xp = (const ulonglong2*)(xs_f + cur * (Fn * 4));
            #pragma unroll 16
            for (int k = 0; k < Fn; k++) {
                float2 w = wp[k * NPAIR];
                ulonglong2 xv = xp[k];
                unsigned long long w0 = dup2(w.x), w1 = dup2(w.y);
                ffma2(a00, w0, xv.x); ffma2(a01, w0, xv.y);
                ffma2(a10, w1, xv.x); ffma2(a11, w1, xv.y);
            }
            {
                float bi0 = bih[2 * g], bi1 = bih[2 * g + 1];
                float2 u0 = unpk(a00), u1 = unpk(a01), u2 = unpk(a10), u3 = unpk(a11);
                xg4[2 * g]     = make_float4(u0.x + bi0, u0.y + bi0, u1.x + bi0, u1.y + bi0);
                xg4[2 * g + 1] = make_float4(u2.x + bi1, u2.y + bi1, u3.x + bi1, u3.y + bi1);
            }

            // ---- hg = h @ W_hh^T ----
            a00 = a01 = a10 = a11 = 0;
            const float2* wq = whh2 + g;
            const ulonglong2* hp = (const ulonglong2*)hs_f;
            #pragma unroll 16
            for (int k = 0; k < Hn; k++) {
                float2 w = wq[k * NPAIR];
                ulonglong2 hv = hp[k];
                unsigned long long w0 = dup2(w.x), w1 = dup2(w.y);
                ffma2(a00, w0, hv.x); ffma2(a01, w0, hv.y);
                ffma2(a10, w1, hv.x); ffma2(a11, w1, hv.y);
            }
            {
                float bh0 = bhh[2 * g], bh1 = bhh[2 * g + 1];
                float2 u0 = unpk(a00), u1 = unpk(a01), u2 = unpk(a10), u3 = unpk(a11);
                hg4[2 * g]     = make_float4(u0.x + bh0, u0.y + bh0, u1.x + bh0, u1.y + bh0);
                hg4[2 * g + 1] = make_float4(u2.x + bh1, u2.y + bh1, u3.x + bh1, u3.y + bh1);
            }
        }

        // write prefetched x(t+1) into the other buffer (not read this step)
        if (pf) xs4[nxt * Fn + tid] = make_float4(p0, p1, p2, p3);

        __syncthreads();

        // ---- gate combine + h update: 81 hidden x 4 batches = 324 items ----
        for (int it = tid; it < Hn * 4; it += NTHR) {
            float xr = xg_f[it],              hr = hg_f[it];
            float xz = xg_f[Hn * 4 + it],     hz = hg_f[Hn * 4 + it];
            float xn = xg_f[2 * Hn * 4 + it], hn = hg_f[2 * Hn * 4 + it];
            float r = sigm(xr + hr);
            float z = sigm(xz + hz);
            float n = tanh_f(xn + r * hn);
            float hold = hs_f[it];
            hs_f[it] = (1.f - z) * n + z * hold;
        }
        __syncthreads();
    }

    // ---- per-batch head stage 1: out8 = silu(h_last @ fc_w^T + fc_b) ----
    if (tid < 32) {
        int b = tid >> 3, f = tid & 7;
        float a = fc_b[f];
        #pragma unroll 27
        for (int j = 0; j < Hn; j++) a += hs_f[j * 4 + b] * fc_w[f * Hn + j];
        a = a * sigm(a);  // silu
        g_h8[(b0 + b) * 8 + f] = a;
    }
}

// =====================================================================
// Kernel 2: BN(8) -> fc1 -> silu -> BN(4) -> fc2. One CTA, 512 threads.
// (Batch-norm needs full-batch statistics -> separate kernel.)
// =====================================================================
__global__ void __launch_bounds__(Bn) head_kernel(
    const float* __restrict__ g1, const float* __restrict__ beta1,
    const float* __restrict__ fc1_w, const float* __restrict__ fc1_b,
    const float* __restrict__ g2, const float* __restrict__ beta2,
    const float* __restrict__ fc2_w, const float* __restrict__ fc2_b,
    float* __restrict__ out)
{
    __shared__ float s8[Bn * 8];
    __shared__ float s4[Bn * 4];
    __shared__ float mu1[8], iv1[8], mu2[4], iv2[4];
    const int tid = threadIdx.x;

    for (int i = tid; i < Bn * 8; i += Bn) s8[i] = g_h8[i];
    __syncthreads();

    if (tid < 8) {
        float s = 0.f, ss = 0.f;
        for (int b = 0; b < Bn; b++) { float v = s8[b * 8 + tid]; s += v; ss += v * v; }
        float m = s * (1.f / Bn);
        float var = ss * (1.f / Bn) - m * m;   // biased variance (jnp.var)
        mu1[tid] = m;
        iv1[tid] = rsqrtf(var + 1e-5f);
    }
    __syncthreads();

    {
        int b = tid;
        float y[8];
        #pragma unroll
        for (int f = 0; f < 8; f++)
            y[f] = (s8[b * 8 + f] - mu1[f]) * iv1[f] * g1[f] + beta1[f];
        #pragma unroll
        for (int o = 0; o < 4; o++) {
            float a = fc1_b[o];
            #pragma unroll
            for (int f = 0; f < 8; f++) a += y[f] * fc1_w[o * 8 + f];
            a = a * sigm(a);  // silu
            s4[b * 4 + o] = a;
        }
    }
    __syncthreads();

    if (tid < 4) {
        float s = 0.f, ss = 0.f;
        for (int b = 0; b < Bn; b++) { float v = s4[b * 4 + tid]; s += v; ss += v * v; }
        float m = s * (1.f / Bn);
        float var = ss * (1.f / Bn) - m * m;
        mu2[tid] = m;
        iv2[tid] = rsqrtf(var + 1e-5f);
    }
    __syncthreads();

    {
        int b = tid;
        float a = fc2_b[0];
        #pragma unroll
        for (int o = 0; o < 4; o++)
            a += ((s4[b * 4 + o] - mu2[o]) * iv2[o] * g2[o] + beta2[o]) * fc2_w[o];
        out[b] = a;
    }
}

// =====================================================================
extern "C" void kernel_launch(void* const* d_in, const int* in_sizes, int n_in,
                              void* d_out, int out_size) {
    const float* x     = (const float*)d_in[0];
    const float* W_ih  = (const float*)d_in[1];
    const float* W_hh  = (const float*)d_in[2];
    const float* b_ih  = (const float*)d_in[3];
    const float* b_hh  = (const float*)d_in[4];
    const float* fc_w  = (const float*)d_in[5];
    const float* fc_b  = (const float*)d_in[6];
    const float* g1    = (const float*)d_in[7];
    const float* beta1 = (const float*)d_in[8];
    const float* fc1_w = (const float*)d_in[9];
    const float* fc1_b = (const float*)d_in[10];
    const float* g2    = (const float*)d_in[11];
    const float* beta2 = (const float*)d_in[12];
    const float* fc2_w = (const float*)d_in[13];
    const float* fc2_b = (const float*)d_in[14];
    float* out = (float*)d_out;

    cudaFuncSetAttribute(gru_kernel, cudaFuncAttributeMaxDynamicSharedMemorySize, SMEM_BYTES);

    gru_kernel<<<NCTA, NTHR, SMEM_BYTES>>>(x, W_ih, W_hh, b_ih, b_hh, fc_w, fc_b);
    head_kernel<<<1, Bn>>>(g1, beta1, fc1_w, fc1_b, g2, beta2, fc2_w, fc2_b, out);
}